// round 11
// baseline (speedup 1.0000x reference)
#include <cuda_runtime.h>

// Problem constants (fixed by reference: D=64, N=262144)
#define ROWS 129
#define NCOLS 262144
#define STRIDE (NCOLS + 1)      // 262145 == 1 (mod 32): row k misaligned by k mod 32
#define LASTROW 128

#define DBLOCK 256
#define DCHUNK 8192
#define NCH (NCOLS / DCHUNK)    // 32

#define ABLOCK 256
#define NAB (NCOLS / ABLOCK)    // 1024 blocks, one column per thread

__device__ float g_partial[ROWS * NCH];
__device__ float g_t[ROWS];

// ---------------------------------------------------------------------------
// Pass 1 (fused copy + dot, ALIGNED): out[i,:] = Z[i,:] and partials of
// s_i = sum_{j<N} Z[i,j]*Z[128,j]. Each row's window is shifted by
// h = (-row) mod 32 so Z[row] loads and out[row] stores are single-line
// 128B accesses (no 5-sector split on the write stream). Row-128 loads are
// misaligned but L2/L1-hot. Block x==0 covers the head columns [0, h).
// ---------------------------------------------------------------------------
__global__ void tf_pass1(const float* __restrict__ Z, float* __restrict__ out) {
    const int row = blockIdx.y;                        // 0..128
    const int tid = threadIdx.x;
    const int h = (32 - (row & 31)) & 31;              // (row*STRIDE + h) % 32 == 0
    const size_t rowbase = (size_t)row * STRIDE;
    const size_t base = (size_t)blockIdx.x * DCHUNK + h;
    const float* __restrict__ zl = Z + (size_t)LASTROW * STRIDE;

    float acc = 0.0f;
    #pragma unroll 8
    for (int j = tid; j < DCHUNK; j += DBLOCK) {
        const size_t col = base + j;
        if (col < (size_t)NCOLS) {
            const float v = Z[rowbase + col];
            acc = fmaf(v, __ldg(zl + col), acc);
            out[rowbase + col] = v;
        }
    }
    if (blockIdx.x == 0 && tid < h) {                  // head columns [0, h)
        const float v = Z[rowbase + tid];
        acc = fmaf(v, __ldg(zl + tid), acc);
        out[rowbase + tid] = v;
    }

    __shared__ float warp_acc[DBLOCK / 32];
    for (int o = 16; o; o >>= 1) acc += __shfl_down_sync(0xffffffffu, acc, o);
    if ((tid & 31) == 0) warp_acc[tid >> 5] = acc;
    __syncthreads();
    if (tid < 8) {
        float a = warp_acc[tid];
        for (int o = 4; o; o >>= 1) a += __shfl_down_sync(0xffu, a, o, 8);
        if (tid == 0) g_partial[row * NCH + blockIdx.x] = a;
    }
}

// ---------------------------------------------------------------------------
// Pass 2 (tiny, 1 block): s = reduce(partials); t = Q^T s;
// plus the entire j = N column of out (copy rows 0..127, update row 128).
// ---------------------------------------------------------------------------
__global__ void tf_solve(const float* __restrict__ Z, const float* __restrict__ Q,
                         float* __restrict__ out) {
    __shared__ float s_sh[ROWS];
    __shared__ float t_sh[ROWS];
    const int i = threadIdx.x;

    if (i < ROWS) {
        float a = 0.0f;
        #pragma unroll
        for (int c = 0; c < NCH; c++) a += g_partial[i * NCH + c];
        s_sh[i] = a;
        if (i < LASTROW)
            out[(size_t)i * STRIDE + NCOLS] = Z[(size_t)i * STRIDE + NCOLS];
    }
    __syncthreads();
    if (i < ROWS) {
        float a = 0.0f;
        #pragma unroll 8
        for (int k = 0; k < ROWS; k++) a = fmaf(s_sh[k], Q[k * ROWS + i], a);
        g_t[i] = a;
        t_sh[i] = a;
    }
    __syncthreads();
    if (i < 32) {   // out[128, N] = Z[128,N] + (sum_k t_k * Z[k,N]) / N
        float a = 0.0f;
        for (int k = i; k < ROWS; k += 32)
            a = fmaf(t_sh[k], Z[(size_t)k * STRIDE + NCOLS], a);
        for (int o = 16; o; o >>= 1) a += __shfl_down_sync(0xffffffffu, a, o);
        if (i == 0)
            out[(size_t)LASTROW * STRIDE + NCOLS] =
                Z[(size_t)LASTROW * STRIDE + NCOLS] + a * (1.0f / (float)NCOLS);
    }
}

// ---------------------------------------------------------------------------
// Pass 3 (row-128 apply, read-only + 1MB write): one column per thread.
// out[128,j] = Z[128,j] + (sum_k t_k * Z[k,j]) / N.
// Two independent fma chains (even/odd k) + unroll 8 -> 16 loads in flight
// per thread instead of 8 (R3 had a single serial chain).
// ---------------------------------------------------------------------------
__global__ void tf_apply(const float* __restrict__ Z, float* __restrict__ out) {
    __shared__ float t_sh[ROWS];
    if (threadIdx.x < ROWS) t_sh[threadIdx.x] = g_t[threadIdx.x];
    __syncthreads();

    const size_t j = (size_t)blockIdx.x * ABLOCK + threadIdx.x;   // 0 .. N-1
    const float* __restrict__ zc = Z + j;

    float a0 = 0.0f, a1 = 0.0f;
    #pragma unroll 8
    for (int k = 0; k < LASTROW; k += 2) {
        a0 = fmaf(t_sh[k],     zc[(size_t)k * STRIDE],       a0);
        a1 = fmaf(t_sh[k + 1], zc[(size_t)(k + 1) * STRIDE], a1);
    }
    const float v = zc[(size_t)LASTROW * STRIDE];
    a0 = fmaf(t_sh[LASTROW], v, a0);
    out[(size_t)LASTROW * STRIDE + j] = v + (a0 + a1) * (1.0f / (float)NCOLS);
}

extern "C" void kernel_launch(void* const* d_in, const int* in_sizes, int n_in,
                              void* d_out, int out_size) {
    const float* Z = (const float*)d_in[0];
    // d_in[1] is P: structurally a single 1 at [-1,-1] (exploited analytically)
    const float* Q = (const float*)d_in[2];
    float* out = (float*)d_out;

    dim3 g1(NCH, ROWS);                  // 32 x 129 = 4128 blocks
    tf_pass1<<<g1, DBLOCK>>>(Z, out);
    tf_solve<<<1, 256>>>(Z, Q, out);
    tf_apply<<<NAB, ABLOCK>>>(Z, out);   // 1024 blocks x 256 threads
}

// round 12
// speedup vs baseline: 1.0193x; 1.0193x over previous
#include <cuda_runtime.h>

// Problem constants (fixed by reference: D=64, N=262144)
#define ROWS 129
#define NCOLS 262144
#define STRIDE (NCOLS + 1)      // 262145 == 1 (mod 32): row k misaligned by k mod 32
#define LASTROW 128

#define DBLOCK 256
#define DCHUNK 8192
#define NCH (NCOLS / DCHUNK)    // 32

#define CH2 2048                // tf_acc column window
#define XB2 (NCOLS / CH2)       // 128
#define GR 8                    // row groups of 16 (rows 0..127)
#define GROWS 16

__device__ float g_partial[ROWS * NCH];
__device__ float g_t[ROWS];
__device__ float g_p[GR * XB2 * CH2];   // 8 MB partial column-sums

// ---------------------------------------------------------------------------
// Pass 1 (fused copy + dot, aligned, guard-free): out[i,:] = Z[i,:] and
// partials of s_i = sum_{j<N} Z[i,j]*Z[128,j]. Window shifted by
// h = (-row) mod 32 -> Z[row] loads and out[row] stores are single 128B
// lines (full sectors on the write stream). Only the LAST block carries a
// bounds check; blocks 0..NCH-2 run an unconditional unrolled body so ptxas
// front-batches the loads. Block 0 additionally covers head cols [0, h).
// ---------------------------------------------------------------------------
__global__ void tf_pass1(const float* __restrict__ Z, float* __restrict__ out) {
    const int row = blockIdx.y;                        // 0..128
    const int tid = threadIdx.x;
    const int h = (32 - (row & 31)) & 31;              // (row*STRIDE + h) % 32 == 0
    const size_t rowbase = (size_t)row * STRIDE;
    const size_t base = (size_t)blockIdx.x * DCHUNK + h;
    const float* __restrict__ zl = Z + (size_t)LASTROW * STRIDE;

    float acc = 0.0f;
    if (blockIdx.x < NCH - 1) {
        #pragma unroll 8
        for (int j = tid; j < DCHUNK; j += DBLOCK) {
            const size_t col = base + j;
            const float v = Z[rowbase + col];
            acc = fmaf(v, __ldg(zl + col), acc);
            out[rowbase + col] = v;
        }
    } else {
        #pragma unroll 8
        for (int j = tid; j < DCHUNK; j += DBLOCK) {
            const size_t col = base + j;
            if (col < (size_t)NCOLS) {
                const float v = Z[rowbase + col];
                acc = fmaf(v, __ldg(zl + col), acc);
                out[rowbase + col] = v;
            }
        }
    }
    if (blockIdx.x == 0 && tid < h) {                  // head columns [0, h)
        const float v = Z[rowbase + tid];
        acc = fmaf(v, __ldg(zl + tid), acc);
        out[rowbase + tid] = v;
    }

    __shared__ float warp_acc[DBLOCK / 32];
    for (int o = 16; o; o >>= 1) acc += __shfl_down_sync(0xffffffffu, acc, o);
    if ((tid & 31) == 0) warp_acc[tid >> 5] = acc;
    __syncthreads();
    if (tid < 8) {
        float a = warp_acc[tid];
        for (int o = 4; o; o >>= 1) a += __shfl_down_sync(0xffu, a, o, 8);
        if (tid == 0) g_partial[row * NCH + blockIdx.x] = a;
    }
}

// ---------------------------------------------------------------------------
// Pass 2 (tiny, 1 block): s = reduce(partials); t = Q^T s;
// plus the entire j = N column of out (copy rows 0..127, update row 128).
// ---------------------------------------------------------------------------
__global__ void tf_solve(const float* __restrict__ Z, const float* __restrict__ Q,
                         float* __restrict__ out) {
    __shared__ float s_sh[ROWS];
    __shared__ float t_sh[ROWS];
    const int i = threadIdx.x;

    if (i < ROWS) {
        float a = 0.0f;
        #pragma unroll
        for (int c = 0; c < NCH; c++) a += g_partial[i * NCH + c];
        s_sh[i] = a;
        if (i < LASTROW)
            out[(size_t)i * STRIDE + NCOLS] = Z[(size_t)i * STRIDE + NCOLS];
    }
    __syncthreads();
    if (i < ROWS) {
        float a = 0.0f;
        #pragma unroll 8
        for (int k = 0; k < ROWS; k++) a = fmaf(s_sh[k], Q[k * ROWS + i], a);
        g_t[i] = a;
        t_sh[i] = a;
    }
    __syncthreads();
    if (i < 32) {   // out[128, N] = Z[128,N] + (sum_k t_k * Z[k,N]) / N
        float a = 0.0f;
        for (int k = i; k < ROWS; k += 32)
            a = fmaf(t_sh[k], Z[(size_t)k * STRIDE + NCOLS], a);
        for (int o = 16; o; o >>= 1) a += __shfl_down_sync(0xffffffffu, a, o);
        if (i == 0)
            out[(size_t)LASTROW * STRIDE + NCOLS] =
                Z[(size_t)LASTROW * STRIDE + NCOLS] + a * (1.0f / (float)NCOLS);
    }
}

// ---------------------------------------------------------------------------
// Pass 3a (tiled row-streaming weighted sum): block (x, g) streams rows
// 16g..16g+15 over cols [x*2048, (x+1)*2048) in 8KB contiguous bursts
// (DRAM row-buffer friendly). Each thread owns 8 fixed columns -> 8 register
// accumulators, no smem RMW, no barriers, no guards. Partials to g_p.
// ---------------------------------------------------------------------------
__global__ void tf_acc(const float* __restrict__ Z) {
    const int x = blockIdx.x;           // 0..127
    const int g = blockIdx.y;           // 0..7
    const int tid = threadIdx.x;

    __shared__ float t_sh[GROWS];
    if (tid < GROWS) t_sh[tid] = g_t[GROWS * g + tid];
    __syncthreads();

    float a0 = 0.f, a1 = 0.f, a2 = 0.f, a3 = 0.f;
    float a4 = 0.f, a5 = 0.f, a6 = 0.f, a7 = 0.f;

    #pragma unroll 2
    for (int r = 0; r < GROWS; r++) {
        const float* __restrict__ zr =
            Z + (size_t)(GROWS * g + r) * STRIDE + (size_t)x * CH2;
        const float t = t_sh[r];
        a0 = fmaf(t, __ldg(zr + 0 * 256 + tid), a0);
        a1 = fmaf(t, __ldg(zr + 1 * 256 + tid), a1);
        a2 = fmaf(t, __ldg(zr + 2 * 256 + tid), a2);
        a3 = fmaf(t, __ldg(zr + 3 * 256 + tid), a3);
        a4 = fmaf(t, __ldg(zr + 4 * 256 + tid), a4);
        a5 = fmaf(t, __ldg(zr + 5 * 256 + tid), a5);
        a6 = fmaf(t, __ldg(zr + 6 * 256 + tid), a6);
        a7 = fmaf(t, __ldg(zr + 7 * 256 + tid), a7);
    }

    float* gp = g_p + ((size_t)g * XB2 + x) * CH2;
    gp[0 * 256 + tid] = a0;  gp[1 * 256 + tid] = a1;
    gp[2 * 256 + tid] = a2;  gp[3 * 256 + tid] = a3;
    gp[4 * 256 + tid] = a4;  gp[5 * 256 + tid] = a5;
    gp[6 * 256 + tid] = a6;  gp[7 * 256 + tid] = a7;
}

// ---------------------------------------------------------------------------
// Pass 3b: out[128,j] = Z[128,j] + (sum_g g_p[g][j] + t128*Z[128,j]) / N.
// ---------------------------------------------------------------------------
__global__ void tf_fin(const float* __restrict__ Z, float* __restrict__ out) {
    __shared__ float t128;
    if (threadIdx.x == 0) t128 = g_t[LASTROW];
    __syncthreads();

    const size_t j = (size_t)blockIdx.x * 256 + threadIdx.x;   // [0, N)
    float a = 0.0f;
    #pragma unroll
    for (int g = 0; g < GR; g++)
        a += g_p[(size_t)g * (XB2 * CH2) + j];                 // XB2*CH2 == NCOLS
    const float v = __ldg(Z + (size_t)LASTROW * STRIDE + j);
    a = fmaf(t128, v, a);
    out[(size_t)LASTROW * STRIDE + j] = v + a * (1.0f / (float)NCOLS);
}

extern "C" void kernel_launch(void* const* d_in, const int* in_sizes, int n_in,
                              void* d_out, int out_size) {
    const float* Z = (const float*)d_in[0];
    // d_in[1] is P: structurally a single 1 at [-1,-1] (exploited analytically)
    const float* Q = (const float*)d_in[2];
    float* out = (float*)d_out;

    dim3 g1(NCH, ROWS);                  // 32 x 129 = 4128 blocks
    tf_pass1<<<g1, DBLOCK>>>(Z, out);
    tf_solve<<<1, 256>>>(Z, Q, out);
    dim3 ga(XB2, GR);                    // 128 x 8 = 1024 blocks
    tf_acc<<<ga, 256>>>(Z);
    tf_fin<<<NCOLS / 256, 256>>>(Z, out);
}

// round 13
// speedup vs baseline: 1.0215x; 1.0021x over previous
#include <cuda_runtime.h>

// Problem constants (fixed by reference: D=64, N=262144)
#define ROWS 129
#define NCOLS 262144
#define STRIDE (NCOLS + 1)      // 262145 == 1 (mod 32): row k misaligned by k mod 32
#define LASTROW 128

#define DBLOCK 256
#define DCHUNK 8192
#define NCH (NCOLS / DCHUNK)    // 32

#define CH2 2048                // tf_acc column window
#define XB2 (NCOLS / CH2)       // 128
#define GR 8                    // row groups of 16 (rows 0..127)
#define GROWS 16

__device__ float g_partial[ROWS * NCH];
__device__ float g_t[ROWS];
__device__ float g_p[GR * XB2 * CH2];   // 8 MB partial column-sums

// ---------------------------------------------------------------------------
// Pass 1 (fused copy + dot, aligned, guard-free): out[i,:] = Z[i,:] and
// partials of s_i = sum_{j<N} Z[i,j]*Z[128,j]. Window shifted by
// h = (-row) mod 32 -> Z[row] loads and out[row] stores are single 128B
// lines (full sectors on the write stream). Only the LAST block carries a
// bounds check; blocks 0..NCH-2 run an unconditional unrolled body so ptxas
// front-batches the loads. Block 0 additionally covers head cols [0, h).
// ---------------------------------------------------------------------------
__global__ void tf_pass1(const float* __restrict__ Z, float* __restrict__ out) {
    const int row = blockIdx.y;                        // 0..128
    const int tid = threadIdx.x;
    const int h = (32 - (row & 31)) & 31;              // (row*STRIDE + h) % 32 == 0
    const size_t rowbase = (size_t)row * STRIDE;
    const size_t base = (size_t)blockIdx.x * DCHUNK + h;
    const float* __restrict__ zl = Z + (size_t)LASTROW * STRIDE;

    float acc = 0.0f;
    if (blockIdx.x < NCH - 1) {
        #pragma unroll 8
        for (int j = tid; j < DCHUNK; j += DBLOCK) {
            const size_t col = base + j;
            const float v = Z[rowbase + col];
            acc = fmaf(v, __ldg(zl + col), acc);
            out[rowbase + col] = v;
        }
    } else {
        #pragma unroll 8
        for (int j = tid; j < DCHUNK; j += DBLOCK) {
            const size_t col = base + j;
            if (col < (size_t)NCOLS) {
                const float v = Z[rowbase + col];
                acc = fmaf(v, __ldg(zl + col), acc);
                out[rowbase + col] = v;
            }
        }
    }
    if (blockIdx.x == 0 && tid < h) {                  // head columns [0, h)
        const float v = Z[rowbase + tid];
        acc = fmaf(v, __ldg(zl + tid), acc);
        out[rowbase + tid] = v;
    }

    __shared__ float warp_acc[DBLOCK / 32];
    for (int o = 16; o; o >>= 1) acc += __shfl_down_sync(0xffffffffu, acc, o);
    if ((tid & 31) == 0) warp_acc[tid >> 5] = acc;
    __syncthreads();
    if (tid < 8) {
        float a = warp_acc[tid];
        for (int o = 4; o; o >>= 1) a += __shfl_down_sync(0xffu, a, o, 8);
        if (tid == 0) g_partial[row * NCH + blockIdx.x] = a;
    }
}

// ---------------------------------------------------------------------------
// Pass 2 (tiny, 1 block): s = reduce(partials); t = Q^T s;
// plus the entire j = N column of out (copy rows 0..127, update row 128).
// ---------------------------------------------------------------------------
__global__ void tf_solve(const float* __restrict__ Z, const float* __restrict__ Q,
                         float* __restrict__ out) {
    __shared__ float s_sh[ROWS];
    __shared__ float t_sh[ROWS];
    const int i = threadIdx.x;

    if (i < ROWS) {
        float a = 0.0f;
        #pragma unroll
        for (int c = 0; c < NCH; c++) a += g_partial[i * NCH + c];
        s_sh[i] = a;
        if (i < LASTROW)
            out[(size_t)i * STRIDE + NCOLS] = Z[(size_t)i * STRIDE + NCOLS];
    }
    __syncthreads();
    if (i < ROWS) {
        float a = 0.0f;
        #pragma unroll 8
        for (int k = 0; k < ROWS; k++) a = fmaf(s_sh[k], Q[k * ROWS + i], a);
        g_t[i] = a;
        t_sh[i] = a;
    }
    __syncthreads();
    if (i < 32) {   // out[128, N] = Z[128,N] + (sum_k t_k * Z[k,N]) / N
        float a = 0.0f;
        for (int k = i; k < ROWS; k += 32)
            a = fmaf(t_sh[k], Z[(size_t)k * STRIDE + NCOLS], a);
        for (int o = 16; o; o >>= 1) a += __shfl_down_sync(0xffffffffu, a, o);
        if (i == 0)
            out[(size_t)LASTROW * STRIDE + NCOLS] =
                Z[(size_t)LASTROW * STRIDE + NCOLS] + a * (1.0f / (float)NCOLS);
    }
}

// ---------------------------------------------------------------------------
// Pass 3a (tiled row-streaming weighted sum): block (x, g) streams rows
// 16g..16g+15 over cols [x*2048, (x+1)*2048) in 8KB contiguous bursts
// (DRAM row-buffer friendly). Each thread owns 8 fixed columns -> 8 register
// accumulators, no smem RMW, no barriers, no guards. Partials to g_p.
// ---------------------------------------------------------------------------
__global__ void tf_acc(const float* __restrict__ Z) {
    const int x = blockIdx.x;           // 0..127
    const int g = blockIdx.y;           // 0..7
    const int tid = threadIdx.x;

    __shared__ float t_sh[GROWS];
    if (tid < GROWS) t_sh[tid] = g_t[GROWS * g + tid];
    __syncthreads();

    float a0 = 0.f, a1 = 0.f, a2 = 0.f, a3 = 0.f;
    float a4 = 0.f, a5 = 0.f, a6 = 0.f, a7 = 0.f;

    #pragma unroll 2
    for (int r = 0; r < GROWS; r++) {
        const float* __restrict__ zr =
            Z + (size_t)(GROWS * g + r) * STRIDE + (size_t)x * CH2;
        const float t = t_sh[r];
        a0 = fmaf(t, __ldg(zr + 0 * 256 + tid), a0);
        a1 = fmaf(t, __ldg(zr + 1 * 256 + tid), a1);
        a2 = fmaf(t, __ldg(zr + 2 * 256 + tid), a2);
        a3 = fmaf(t, __ldg(zr + 3 * 256 + tid), a3);
        a4 = fmaf(t, __ldg(zr + 4 * 256 + tid), a4);
        a5 = fmaf(t, __ldg(zr + 5 * 256 + tid), a5);
        a6 = fmaf(t, __ldg(zr + 6 * 256 + tid), a6);
        a7 = fmaf(t, __ldg(zr + 7 * 256 + tid), a7);
    }

    float* gp = g_p + ((size_t)g * XB2 + x) * CH2;
    gp[0 * 256 + tid] = a0;  gp[1 * 256 + tid] = a1;
    gp[2 * 256 + tid] = a2;  gp[3 * 256 + tid] = a3;
    gp[4 * 256 + tid] = a4;  gp[5 * 256 + tid] = a5;
    gp[6 * 256 + tid] = a6;  gp[7 * 256 + tid] = a7;
}

// ---------------------------------------------------------------------------
// Pass 3b: out[128,j] = Z[128,j] + (sum_g g_p[g][j] + t128*Z[128,j]) / N.
// ---------------------------------------------------------------------------
__global__ void tf_fin(const float* __restrict__ Z, float* __restrict__ out) {
    __shared__ float t128;
    if (threadIdx.x == 0) t128 = g_t[LASTROW];
    __syncthreads();

    const size_t j = (size_t)blockIdx.x * 256 + threadIdx.x;   // [0, N)
    float a = 0.0f;
    #pragma unroll
    for (int g = 0; g < GR; g++)
        a += g_p[(size_t)g * (XB2 * CH2) + j];                 // XB2*CH2 == NCOLS
    const float v = __ldg(Z + (size_t)LASTROW * STRIDE + j);
    a = fmaf(t128, v, a);
    out[(size_t)LASTROW * STRIDE + j] = v + a * (1.0f / (float)NCOLS);
}

extern "C" void kernel_launch(void* const* d_in, const int* in_sizes, int n_in,
                              void* d_out, int out_size) {
    const float* Z = (const float*)d_in[0];
    // d_in[1] is P: structurally a single 1 at [-1,-1] (exploited analytically)
    const float* Q = (const float*)d_in[2];
    float* out = (float*)d_out;

    dim3 g1(NCH, ROWS);                  // 32 x 129 = 4128 blocks
    tf_pass1<<<g1, DBLOCK>>>(Z, out);
    tf_solve<<<1, 256>>>(Z, Q, out);
    dim3 ga(XB2, GR);                    // 128 x 8 = 1024 blocks
    tf_acc<<<ga, 256>>>(Z);
    tf_fin<<<NCOLS / 256, 256>>>(Z, out);
}

// round 14
// speedup vs baseline: 1.2655x; 1.2389x over previous
#include <cuda_runtime.h>

// Problem constants (fixed by reference: D=64, N=262144)
#define ROWS 129
#define NCOLS 262144
#define STRIDE (NCOLS + 1)
#define LASTROW 128

#define BLOCK 256
#define CHUNK 8192
#define NCH (NCOLS / CHUNK)     // 32

#define CH2 2048                // tf_acc column window
#define XB2 (NCOLS / CH2)       // 128
#define GR 8                    // row groups of 16 (rows 0..127)
#define GROWS 16

__device__ float g_partial[ROWS * NCH];
__device__ float g_t[ROWS];
__device__ float g_p[GR * XB2 * CH2];   // 8 MB partial column-sums

// ---------------------------------------------------------------------------
// Pass 1 — PROVEN (R3, 46.8us): fused copy + dot partials, unshifted.
// out[i,:] = Z[i,:], partial of s_i = sum_{j<N} Z[i,j]*Z[128,j].
// ---------------------------------------------------------------------------
__global__ void tf_pass1(const float* __restrict__ Z, float* __restrict__ out) {
    const int row = blockIdx.y;          // 0..128
    const int c   = blockIdx.x;          // 0..31
    const size_t j0 = (size_t)c * CHUNK;

    const float* __restrict__ zr = Z + (size_t)row * STRIDE + j0;
    const float* __restrict__ zl = Z + (size_t)(ROWS - 1) * STRIDE + j0;
    float* __restrict__ orow = out + (size_t)row * STRIDE + j0;

    float acc = 0.0f;
    #pragma unroll 4
    for (int j = threadIdx.x; j < CHUNK; j += BLOCK) {
        float a = zr[j];
        float b = zl[j];
        acc = fmaf(a, b, acc);
        orow[j] = a;                     // fused copy of Z -> out
    }

    __shared__ float sh[BLOCK];
    sh[threadIdx.x] = acc;
    __syncthreads();
    for (int s = BLOCK / 2; s > 0; s >>= 1) {
        if (threadIdx.x < s) sh[threadIdx.x] += sh[threadIdx.x + s];
        __syncthreads();
    }
    if (threadIdx.x == 0) g_partial[row * NCH + c] = sh[0];
}

// ---------------------------------------------------------------------------
// Pass 2 (tiny, 1 block): s = reduce(partials); t = Q^T s;
// plus the entire j = N column of out (copy rows 0..127, update row 128).
// ---------------------------------------------------------------------------
__global__ void tf_solve(const float* __restrict__ Z, const float* __restrict__ Q,
                         float* __restrict__ out) {
    __shared__ float s_sh[ROWS];
    __shared__ float t_sh[ROWS];
    const int i = threadIdx.x;

    if (i < ROWS) {
        float a = 0.0f;
        #pragma unroll
        for (int c = 0; c < NCH; c++) a += g_partial[i * NCH + c];
        s_sh[i] = a;
        if (i < LASTROW)
            out[(size_t)i * STRIDE + NCOLS] = Z[(size_t)i * STRIDE + NCOLS];
    }
    __syncthreads();
    if (i < ROWS) {
        float a = 0.0f;
        #pragma unroll 8
        for (int k = 0; k < ROWS; k++) a = fmaf(s_sh[k], Q[k * ROWS + i], a);
        g_t[i] = a;
        t_sh[i] = a;
    }
    __syncthreads();
    if (i < 32) {   // out[128, N] = Z[128,N] + (sum_k t_k * Z[k,N]) / N
        float a = 0.0f;
        for (int k = i; k < ROWS; k += 32)
            a = fmaf(t_sh[k], Z[(size_t)k * STRIDE + NCOLS], a);
        for (int o = 16; o; o >>= 1) a += __shfl_down_sync(0xffffffffu, a, o);
        if (i == 0)
            out[(size_t)LASTROW * STRIDE + NCOLS] =
                Z[(size_t)LASTROW * STRIDE + NCOLS] + a * (1.0f / (float)NCOLS);
    }
}

// ---------------------------------------------------------------------------
// Pass 3a (tiled row-streaming weighted sum): block (x, g) streams rows
// 16g..16g+15 over cols [x*2048, (x+1)*2048) in contiguous 8KB bursts.
// Each thread owns 8 fixed columns -> 8 register accumulators, no smem RMW,
// no barriers, no guards. Partials to g_p (8 MB).
// ---------------------------------------------------------------------------
__global__ void tf_acc(const float* __restrict__ Z) {
    const int x = blockIdx.x;           // 0..127
    const int g = blockIdx.y;           // 0..7
    const int tid = threadIdx.x;

    __shared__ float t_sh[GROWS];
    if (tid < GROWS) t_sh[tid] = g_t[GROWS * g + tid];
    __syncthreads();

    float a0 = 0.f, a1 = 0.f, a2 = 0.f, a3 = 0.f;
    float a4 = 0.f, a5 = 0.f, a6 = 0.f, a7 = 0.f;

    #pragma unroll 2
    for (int r = 0; r < GROWS; r++) {
        const float* __restrict__ zr =
            Z + (size_t)(GROWS * g + r) * STRIDE + (size_t)x * CH2;
        const float t = t_sh[r];
        a0 = fmaf(t, __ldg(zr + 0 * 256 + tid), a0);
        a1 = fmaf(t, __ldg(zr + 1 * 256 + tid), a1);
        a2 = fmaf(t, __ldg(zr + 2 * 256 + tid), a2);
        a3 = fmaf(t, __ldg(zr + 3 * 256 + tid), a3);
        a4 = fmaf(t, __ldg(zr + 4 * 256 + tid), a4);
        a5 = fmaf(t, __ldg(zr + 5 * 256 + tid), a5);
        a6 = fmaf(t, __ldg(zr + 6 * 256 + tid), a6);
        a7 = fmaf(t, __ldg(zr + 7 * 256 + tid), a7);
    }

    float* gp = g_p + ((size_t)g * XB2 + x) * CH2;
    gp[0 * 256 + tid] = a0;  gp[1 * 256 + tid] = a1;
    gp[2 * 256 + tid] = a2;  gp[3 * 256 + tid] = a3;
    gp[4 * 256 + tid] = a4;  gp[5 * 256 + tid] = a5;
    gp[6 * 256 + tid] = a6;  gp[7 * 256 + tid] = a7;
}

// ---------------------------------------------------------------------------
// Pass 3b (float4): out[128,j] = Z[128,j] + (sum_g g_p[g][j] + t128*Z[128,j])/N.
// Row 128 base is 16B-aligned (128*STRIDE % 4 == 0); g_p rows are aligned.
// 512 blocks x 128 threads, one float4 per thread, 9 independent vector loads.
// ---------------------------------------------------------------------------
__global__ void tf_fin(const float* __restrict__ Z, float* __restrict__ out) {
    __shared__ float t128;
    if (threadIdx.x == 0) t128 = g_t[LASTROW];
    __syncthreads();

    const size_t j = ((size_t)blockIdx.x * 128 + threadIdx.x) * 4;   // [0, N)
    float4 a = make_float4(0.f, 0.f, 0.f, 0.f);
    #pragma unroll
    for (int g = 0; g < GR; g++) {
        const float4 p = *(const float4*)(g_p + (size_t)g * NCOLS + j);
        a.x += p.x; a.y += p.y; a.z += p.z; a.w += p.w;
    }
    const float4 v = *(const float4*)(Z + (size_t)LASTROW * STRIDE + j);
    const float inv_n = 1.0f / (float)NCOLS;
    float4 r;
    r.x = v.x + fmaf(t128, v.x, a.x) * inv_n;
    r.y = v.y + fmaf(t128, v.y, a.y) * inv_n;
    r.z = v.z + fmaf(t128, v.z, a.z) * inv_n;
    r.w = v.w + fmaf(t128, v.w, a.w) * inv_n;
    *(float4*)(out + (size_t)LASTROW * STRIDE + j) = r;
}

extern "C" void kernel_launch(void* const* d_in, const int* in_sizes, int n_in,
                              void* d_out, int out_size) {
    const float* Z = (const float*)d_in[0];
    // d_in[1] is P: structurally a single 1 at [-1,-1] (exploited analytically)
    const float* Q = (const float*)d_in[2];
    float* out = (float*)d_out;

    dim3 g1(NCH, ROWS);                  // 32 x 129 = 4128 blocks
    tf_pass1<<<g1, BLOCK>>>(Z, out);
    tf_solve<<<1, 256>>>(Z, Q, out);
    dim3 ga(XB2, GR);                    // 128 x 8 = 1024 blocks
    tf_acc<<<ga, 256>>>(Z);
    tf_fin<<<512, 128>>>(Z, out);        // 512 x 128, float4 per thread
}

// round 15
// speedup vs baseline: 1.3172x; 1.0408x over previous
#include <cuda_runtime.h>

// Problem constants (fixed by reference: D=64, N=262144)
#define ROWS 129
#define NCOLS 262144
#define STRIDE (NCOLS + 1)
#define LASTROW 128

#define BLOCK 256
#define CHUNK 8192
#define NCH (NCOLS / CHUNK)     // 32

#define ABLOCK 256
#define NAB (NCOLS / ABLOCK)    // 1024 blocks, one column per thread

__device__ float g_partial[ROWS * NCH];
__device__ float g_t[ROWS];

// ---------------------------------------------------------------------------
// Pass 1 — PROVEN (R3, 46.8us): fused copy + dot partials.
// out[i,:] = Z[i,:], partial of s_i = sum_{j<N} Z[i,j]*Z[128,j].
// Side effect we now exploit: at exit, L2 is full of dirty `out` lines.
// ---------------------------------------------------------------------------
__global__ void tf_pass1(const float* __restrict__ Z, float* __restrict__ out) {
    const int row = blockIdx.y;          // 0..128
    const int c   = blockIdx.x;          // 0..31
    const size_t j0 = (size_t)c * CHUNK;

    const float* __restrict__ zr = Z + (size_t)row * STRIDE + j0;
    const float* __restrict__ zl = Z + (size_t)(ROWS - 1) * STRIDE + j0;
    float* __restrict__ orow = out + (size_t)row * STRIDE + j0;

    float acc = 0.0f;
    #pragma unroll 4
    for (int j = threadIdx.x; j < CHUNK; j += BLOCK) {
        float a = zr[j];
        float b = zl[j];
        acc = fmaf(a, b, acc);
        orow[j] = a;                     // fused copy of Z -> out
    }

    __shared__ float sh[BLOCK];
    sh[threadIdx.x] = acc;
    __syncthreads();
    for (int s = BLOCK / 2; s > 0; s >>= 1) {
        if (threadIdx.x < s) sh[threadIdx.x] += sh[threadIdx.x + s];
        __syncthreads();
    }
    if (threadIdx.x == 0) g_partial[row * NCH + c] = sh[0];
}

// ---------------------------------------------------------------------------
// Pass 2 (tiny, 1 block): s = reduce(partials); t = Q^T s;
// plus the entire j = N column of out (copy rows 0..127, update row 128).
// ---------------------------------------------------------------------------
__global__ void tf_solve(const float* __restrict__ Z, const float* __restrict__ Q,
                         float* __restrict__ out) {
    __shared__ float s_sh[ROWS];
    __shared__ float t_sh[ROWS];
    const int i = threadIdx.x;

    if (i < ROWS) {
        float a = 0.0f;
        #pragma unroll
        for (int c = 0; c < NCH; c++) a += g_partial[i * NCH + c];
        s_sh[i] = a;
        if (i < LASTROW)
            out[(size_t)i * STRIDE + NCOLS] = Z[(size_t)i * STRIDE + NCOLS];
    }
    __syncthreads();
    if (i < ROWS) {
        float a = 0.0f;
        #pragma unroll 8
        for (int k = 0; k < ROWS; k++) a = fmaf(s_sh[k], Q[k * ROWS + i], a);
        g_t[i] = a;
        t_sh[i] = a;
    }
    __syncthreads();
    if (i < 32) {   // out[128, N] = Z[128,N] + (sum_k t_k * Z[k,N]) / N
        float a = 0.0f;
        for (int k = i; k < ROWS; k += 32)
            a = fmaf(t_sh[k], Z[(size_t)k * STRIDE + NCOLS], a);
        for (int o = 16; o; o >>= 1) a += __shfl_down_sync(0xffffffffu, a, o);
        if (i == 0)
            out[(size_t)LASTROW * STRIDE + NCOLS] =
                Z[(size_t)LASTROW * STRIDE + NCOLS] + a * (1.0f / (float)NCOLS);
    }
}

// ---------------------------------------------------------------------------
// Pass 3 (apply, reads OUT not Z): one column per thread, j < N.
// out[128,j] += (sum_k t_k * out[k,j]) / N   -- out[k,j] == Z[k,j] here.
// The out lines are dirty/resident in L2 from pass1 -> reads are L2 hits;
// DRAM during this pass is dominated by the (unavoidable) dirty write-back.
// Two fma chains for MLP. Each thread reads its own [128,j] before writing.
// ---------------------------------------------------------------------------
__global__ void tf_apply(float* __restrict__ out) {
    __shared__ float t_sh[ROWS];
    if (threadIdx.x < ROWS) t_sh[threadIdx.x] = g_t[threadIdx.x];
    __syncthreads();

    const size_t j = (size_t)blockIdx.x * ABLOCK + threadIdx.x;   // 0 .. N-1
    const float* oc = out + j;

    float a0 = 0.0f, a1 = 0.0f;
    #pragma unroll 8
    for (int k = 0; k < LASTROW; k += 2) {
        a0 = fmaf(t_sh[k],     oc[(size_t)k * STRIDE],       a0);
        a1 = fmaf(t_sh[k + 1], oc[(size_t)(k + 1) * STRIDE], a1);
    }
    const float v = oc[(size_t)LASTROW * STRIDE];
    a0 = fmaf(t_sh[LASTROW], v, a0);
    out[(size_t)LASTROW * STRIDE + j] = v + (a0 + a1) * (1.0f / (float)NCOLS);
}

extern "C" void kernel_launch(void* const* d_in, const int* in_sizes, int n_in,
                              void* d_out, int out_size) {
    const float* Z = (const float*)d_in[0];
    // d_in[1] is P: structurally a single 1 at [-1,-1] (exploited analytically)
    const float* Q = (const float*)d_in[2];
    float* out = (float*)d_out;

    dim3 g1(NCH, ROWS);                  // 32 x 129 = 4128 blocks
    tf_pass1<<<g1, BLOCK>>>(Z, out);
    tf_solve<<<1, 256>>>(Z, Q, out);
    tf_apply<<<NAB, ABLOCK>>>(out);      // 1024 blocks x 256 threads
}

// round 16
// speedup vs baseline: 1.3218x; 1.0035x over previous
#include <cuda_runtime.h>

// Problem constants (fixed by reference: D=64, N=262144)
#define ROWS 129
#define NCOLS 262144
#define STRIDE (NCOLS + 1)
#define LASTROW 128

#define BLOCK 256
#define CHUNK 8192
#define NCH (NCOLS / CHUNK)     // 32

#define ACH 4096                // apply column chunk
#define AXB (NCOLS / ACH)       // 64
#define AGR 17                  // 16 groups of 8 rows + row 128 alone

__device__ float g_partial[ROWS * NCH];
__device__ float g_t[ROWS];

// ---------------------------------------------------------------------------
// Pass 1 — PROVEN (R3, 46.8us): fused copy + dot partials.
// out[i,:] = Z[i,:], partial of s_i = sum_{j<N} Z[i,j]*Z[128,j].
// Also seeds out[128,:] = Z[128,:] for the atomic apply.
// ---------------------------------------------------------------------------
__global__ void tf_pass1(const float* __restrict__ Z, float* __restrict__ out) {
    const int row = blockIdx.y;          // 0..128
    const int c   = blockIdx.x;          // 0..31
    const size_t j0 = (size_t)c * CHUNK;

    const float* __restrict__ zr = Z + (size_t)row * STRIDE + j0;
    const float* __restrict__ zl = Z + (size_t)(ROWS - 1) * STRIDE + j0;
    float* __restrict__ orow = out + (size_t)row * STRIDE + j0;

    float acc = 0.0f;
    #pragma unroll 4
    for (int j = threadIdx.x; j < CHUNK; j += BLOCK) {
        float a = zr[j];
        float b = zl[j];
        acc = fmaf(a, b, acc);
        orow[j] = a;                     // fused copy of Z -> out
    }

    __shared__ float sh[BLOCK];
    sh[threadIdx.x] = acc;
    __syncthreads();
    for (int s = BLOCK / 2; s > 0; s >>= 1) {
        if (threadIdx.x < s) sh[threadIdx.x] += sh[threadIdx.x + s];
        __syncthreads();
    }
    if (threadIdx.x == 0) g_partial[row * NCH + c] = sh[0];
}

// ---------------------------------------------------------------------------
// Pass 2 (tiny, 1 block): s = reduce(partials); t = Q^T s;
// plus the entire j = N column of out (copy rows 0..127, update row 128).
// ---------------------------------------------------------------------------
__global__ void tf_solve(const float* __restrict__ Z, const float* __restrict__ Q,
                         float* __restrict__ out) {
    __shared__ float s_sh[ROWS];
    __shared__ float t_sh[ROWS];
    const int i = threadIdx.x;

    if (i < ROWS) {
        float a = 0.0f;
        #pragma unroll
        for (int c = 0; c < NCH; c++) a += g_partial[i * NCH + c];
        s_sh[i] = a;
        if (i < LASTROW)
            out[(size_t)i * STRIDE + NCOLS] = Z[(size_t)i * STRIDE + NCOLS];
    }
    __syncthreads();
    if (i < ROWS) {
        float a = 0.0f;
        #pragma unroll 8
        for (int k = 0; k < ROWS; k++) a = fmaf(s_sh[k], Q[k * ROWS + i], a);
        g_t[i] = a;
        t_sh[i] = a;
    }
    __syncthreads();
    if (i < 32) {   // out[128, N] = Z[128,N] + (sum_k t_k * Z[k,N]) / N
        float a = 0.0f;
        for (int k = i; k < ROWS; k += 32)
            a = fmaf(t_sh[k], Z[(size_t)k * STRIDE + NCOLS], a);
        for (int o = 16; o; o >>= 1) a += __shfl_down_sync(0xffffffffu, a, o);
        if (i == 0)
            out[(size_t)LASTROW * STRIDE + NCOLS] =
                Z[(size_t)LASTROW * STRIDE + NCOLS] + a * (1.0f / (float)NCOLS);
    }
}

// ---------------------------------------------------------------------------
// Pass 3 (apply, tf_dot-shaped + atomic RED): grid (64 chunks x 17 groups).
// Block (x, g<16): streams rows 8g..8g+7 over cols [x*4096, (x+1)*4096) in
// contiguous bursts; 16 fixed-column register accumulators per thread; then
// atomicAdd(acc * 1/N) into out[128, :] (seeded = Z[128,:] by pass1).
// Block (x, 16): row 128's own term t128 * Z[128,j] / N (L2-hot read).
// Short-lived blocks avoid the long-block L1tex-queue spread penalty.
// ---------------------------------------------------------------------------
__global__ void tf_apply(const float* __restrict__ Z, float* __restrict__ out) {
    const int x = blockIdx.x;            // 0..63
    const int g = blockIdx.y;            // 0..16
    const int tid = threadIdx.x;
    const size_t cbase = (size_t)x * ACH;

    __shared__ float t_sh[8];
    if (g < 16) {
        if (tid < 8) t_sh[tid] = g_t[8 * g + tid];
    } else {
        if (tid == 0) t_sh[0] = g_t[LASTROW];
    }
    __syncthreads();

    float acc[16];
    #pragma unroll
    for (int s = 0; s < 16; s++) acc[s] = 0.0f;

    if (g < 16) {
        #pragma unroll
        for (int r = 0; r < 8; r++) {
            const float* __restrict__ zr =
                Z + (size_t)(8 * g + r) * STRIDE + cbase;
            const float t = t_sh[r];
            #pragma unroll
            for (int s = 0; s < 16; s++)
                acc[s] = fmaf(t, __ldg(zr + s * 256 + tid), acc[s]);
        }
    } else {
        const float* __restrict__ zr = Z + (size_t)LASTROW * STRIDE + cbase;
        const float t = t_sh[0];
        #pragma unroll
        for (int s = 0; s < 16; s++)
            acc[s] = t * __ldg(zr + s * 256 + tid);
    }

    float* __restrict__ orow = out + (size_t)LASTROW * STRIDE + cbase;
    const float inv_n = 1.0f / (float)NCOLS;
    #pragma unroll
    for (int s = 0; s < 16; s++)
        atomicAdd(orow + s * 256 + tid, acc[s] * inv_n);
}

extern "C" void kernel_launch(void* const* d_in, const int* in_sizes, int n_in,
                              void* d_out, int out_size) {
    const float* Z = (const float*)d_in[0];
    // d_in[1] is P: structurally a single 1 at [-1,-1] (exploited analytically)
    const float* Q = (const float*)d_in[2];
    float* out = (float*)d_out;

    dim3 g1(NCH, ROWS);                  // 32 x 129 = 4128 blocks
    tf_pass1<<<g1, BLOCK>>>(Z, out);
    tf_solve<<<1, 256>>>(Z, Q, out);
    dim3 ga(AXB, AGR);                   // 64 x 17 = 1088 blocks
    tf_apply<<<ga, 256>>>(Z, out);
}